// round 3
// baseline (speedup 1.0000x reference)
#include <cuda_runtime.h>
#include <cstdint>
#include <math.h>

// ---------------- problem constants ----------------
#define NA    100000      // atoms
#define NBD   200000      // directed bonds
#define NB    100000      // undirected bonds
#define NANG  400000      // angles
#define NG    2048        // graphs
#define DIM   128         // embed dim
#define HID   256         // hidden dim (2*DIM)
#define NCB   20          // bond RBF centers (arange(0,2,0.1))
#define NCA   32          // angle RBF centers (arange(0,pi,0.1))
#define GAMMA 10.0f
#define LN_EPS 1e-5f

// NO __device__ globals: all scratch lives inside d_out.
// d_out layout: [node region: NA*DIM floats][edge region: NBD*DIM floats]
// Phase E: node region = agg_b, edge region rows [0,NB) = bond_embed, then edge output.
// Phase N: node region = agg_a, then node output (in-place, block-local).

// ---------------- helpers ----------------
__device__ __forceinline__ void red_add_v4(float* addr, float4 v) {
    asm volatile("red.global.add.v4.f32 [%0], {%1, %2, %3, %4};"
                 :: "l"(addr), "f"(v.x), "f"(v.y), "f"(v.z), "f"(v.w)
                 : "memory");
}

__device__ __forceinline__ float warp_sum(float v) {
    #pragma unroll
    for (int o = 16; o > 0; o >>= 1) v += __shfl_xor_sync(0xFFFFFFFFu, v, o);
    return v;
}

// segment length of the (sorted) gid array around index u (gid[u] == g).
// Warp-cooperative outward scan; all control flow warp-uniform.
__device__ __forceinline__ float warp_seg_count(const int* __restrict__ gid,
                                                int M, int u, int g, int lane) {
    int r = u + 1;
    for (;;) {
        int i = r + lane;
        int v = (i < M) ? gid[i] : (g ^ 1);
        unsigned m = __ballot_sync(0xFFFFFFFFu, v != g);
        if (m) { r += __ffs(m) - 1; break; }
        r += 32;
    }
    int l = u - 1;
    for (;;) {
        int i = l - lane;
        int v = (i >= 0) ? gid[i] : (g ^ 1);
        unsigned m = __ballot_sync(0xFFFFFFFFu, v != g);
        if (m) { l -= __ffs(m) - 1; break; }
        l -= 32;
    }
    return (float)(r - l - 1);
}

// ---------------- zero a float4 range ----------------
__global__ void k_zero(float4* __restrict__ p, int n4) {
    int stride = gridDim.x * blockDim.x;
    float4 z = make_float4(0.f, 0.f, 0.f, 0.f);
    for (int i = blockIdx.x * blockDim.x + threadIdx.x; i < n4; i += stride) p[i] = z;
}

// ---------------- block A scatter: agg[dst] += nf[src] + ef[e] ----------------
__global__ void k_scatter_a(const float* __restrict__ nf, const float* __restrict__ ef,
                            const int* __restrict__ src, const int* __restrict__ dst,
                            float* __restrict__ agg) {
    int w = (blockIdx.x * blockDim.x + threadIdx.x) >> 5;
    int lane = threadIdx.x & 31;
    if (w >= NBD) return;
    int s = __ldg(&src[w]);
    int d = __ldg(&dst[w]);
    float4 a = reinterpret_cast<const float4*>(nf + (size_t)s * DIM)[lane];
    float4 b = reinterpret_cast<const float4*>(ef + (size_t)w * DIM)[lane];
    float4 v = make_float4(a.x + b.x, a.y + b.y, a.z + b.z, a.w + b.w);
    red_add_v4(agg + (size_t)d * DIM + lane * 4, v);
}

// ---------------- bond embedding (even directed bonds) -> bond_embed[u] ------
__global__ void k_bond_embed(const float* __restrict__ bond_float,
                             const int* __restrict__ bond_cat,
                             const float* __restrict__ bemb,     // (3,16,DIM)
                             const float* __restrict__ rbfW,     // (20,DIM)
                             const float* __restrict__ rbfb,     // (DIM,)
                             float* __restrict__ bond_embed) {
    int u = (blockIdx.x * blockDim.x + threadIdx.x) >> 5;
    int lane = threadIdx.x & 31;
    if (u >= NB) return;
    int e = 2 * u;
    float x = __ldg(&bond_float[e]);
    float ev = 0.f;
    if (lane < NCB) {
        float dlt = x - 0.1f * (float)lane;
        ev = __expf(-GAMMA * dlt * dlt);
    }
    int c0 = __ldg(&bond_cat[(size_t)e * 3 + 0]);
    int c1 = __ldg(&bond_cat[(size_t)e * 3 + 1]);
    int c2 = __ldg(&bond_cat[(size_t)e * 3 + 2]);

    float4 acc = reinterpret_cast<const float4*>(rbfb)[lane];
    float4 t;
    t = reinterpret_cast<const float4*>(bemb + (size_t)(0 * 16 + c0) * DIM)[lane];
    acc.x += t.x; acc.y += t.y; acc.z += t.z; acc.w += t.w;
    t = reinterpret_cast<const float4*>(bemb + (size_t)(1 * 16 + c1) * DIM)[lane];
    acc.x += t.x; acc.y += t.y; acc.z += t.z; acc.w += t.w;
    t = reinterpret_cast<const float4*>(bemb + (size_t)(2 * 16 + c2) * DIM)[lane];
    acc.x += t.x; acc.y += t.y; acc.z += t.z; acc.w += t.w;

    #pragma unroll
    for (int c = 0; c < NCB; ++c) {
        float ec = __shfl_sync(0xFFFFFFFFu, ev, c);
        float4 wv = reinterpret_cast<const float4*>(rbfW + (size_t)c * DIM)[lane];
        acc.x += ec * wv.x; acc.y += ec * wv.y; acc.z += ec * wv.z; acc.w += ec * wv.w;
    }
    reinterpret_cast<float4*>(bond_embed + (size_t)u * DIM)[lane] = acc;
}

// ---------------- block B scatter: agg[dst] += bond_embed[src] + rbf(angle) ---
__global__ void k_scatter_b(const float* __restrict__ angle_float,
                            const int* __restrict__ src, const int* __restrict__ dst,
                            const float* __restrict__ rbfW,     // (32,DIM)
                            const float* __restrict__ rbfb,
                            const float* __restrict__ bond_embed,
                            float* __restrict__ agg) {
    int a = (blockIdx.x * blockDim.x + threadIdx.x) >> 5;
    int lane = threadIdx.x & 31;
    if (a >= NANG) return;
    float x = __ldg(&angle_float[a]);
    float dlt = x - 0.1f * (float)lane;           // 32 lanes == 32 centers
    float ev = __expf(-GAMMA * dlt * dlt);
    int s = __ldg(&src[a]);
    int d = __ldg(&dst[a]);

    float4 acc = reinterpret_cast<const float4*>(rbfb)[lane];
    float4 be = reinterpret_cast<const float4*>(bond_embed + (size_t)s * DIM)[lane];
    acc.x += be.x; acc.y += be.y; acc.z += be.z; acc.w += be.w;

    #pragma unroll
    for (int c = 0; c < NCA; ++c) {
        float ec = __shfl_sync(0xFFFFFFFFu, ev, c);
        float4 wv = reinterpret_cast<const float4*>(rbfW + (size_t)c * DIM)[lane];
        acc.x += ec * wv.x; acc.y += ec * wv.y; acc.z += ec * wv.z; acc.w += ec * wv.w;
    }
    red_add_v4(agg + (size_t)d * DIM + lane * 4, acc);
}

// ---------------- fused MLP + LN + graphnorm + relu + residual ----------------
// EDGE=0: residual = base[u], write out[u]           (out may alias A, block-local)
// EDGE=1: residual = recomputed bond_embed[u], write out[2u] and out[2u+1]
// BM=32 rows/block, 256 threads. Static smem = 41 KB.
template<int EDGE>
__global__ void __launch_bounds__(256)
k_fused(const float* __restrict__ A,
        const float* __restrict__ w1, const float* __restrict__ b1,
        const float* __restrict__ w2, const float* __restrict__ b2,
        const float* __restrict__ lng, const float* __restrict__ lnb,
        const int* __restrict__ gid,
        const float* __restrict__ base,
        const float* __restrict__ bond_float, const int* __restrict__ bond_cat,
        const float* __restrict__ bemb,
        const float* __restrict__ rbfW, const float* __restrict__ rbfb,
        float* __restrict__ out, int M) {
    constexpr int BM = 32, BK = 8;
    __shared__ float sA[BK][BM];       // 1 KB
    __shared__ float sW[BK][HID];      // 8 KB (stage2 uses cols [0,128))
    __shared__ float sH[BM][HID];      // 32 KB (stage3 reuses as C[32][128])
    const int tid  = threadIdx.x;
    const int lane = tid & 31;
    const int wrp  = tid >> 5;         // 0..7
    const int rowBase = blockIdx.x * BM;

    // ---- stage 1: H = relu(A @ W1 + b1)  (32 x 256) ----
    float acc1[4][8];
    #pragma unroll
    for (int i = 0; i < 4; ++i)
        #pragma unroll
        for (int j = 0; j < 8; ++j) acc1[i][j] = 0.f;

    for (int kt = 0; kt < DIM; kt += BK) {
        if (tid < 64) {
            int r = tid >> 1, c4 = tid & 1;
            float4 v = make_float4(0.f, 0.f, 0.f, 0.f);
            if (rowBase + r < M)
                v = *reinterpret_cast<const float4*>(A + (size_t)(rowBase + r) * DIM + kt + c4 * 4);
            sA[c4 * 4 + 0][r] = v.x; sA[c4 * 4 + 1][r] = v.y;
            sA[c4 * 4 + 2][r] = v.z; sA[c4 * 4 + 3][r] = v.w;
        }
        #pragma unroll
        for (int t = 0; t < 2; ++t) {
            int l = tid + t * 256;            // 0..511
            int k = l >> 6, c4 = l & 63;
            *reinterpret_cast<float4*>(&sW[k][c4 * 4]) =
                *reinterpret_cast<const float4*>(w1 + (size_t)(kt + k) * HID + c4 * 4);
        }
        __syncthreads();
        #pragma unroll
        for (int k = 0; k < BK; ++k) {
            float ra[4];
            #pragma unroll
            for (int i = 0; i < 4; ++i) ra[i] = sA[k][wrp * 4 + i];   // warp-broadcast
            float4 w0 = *reinterpret_cast<const float4*>(&sW[k][lane * 4]);
            float4 w1r = *reinterpret_cast<const float4*>(&sW[k][128 + lane * 4]);
            #pragma unroll
            for (int i = 0; i < 4; ++i) {
                acc1[i][0] += ra[i] * w0.x;  acc1[i][1] += ra[i] * w0.y;
                acc1[i][2] += ra[i] * w0.z;  acc1[i][3] += ra[i] * w0.w;
                acc1[i][4] += ra[i] * w1r.x; acc1[i][5] += ra[i] * w1r.y;
                acc1[i][6] += ra[i] * w1r.z; acc1[i][7] += ra[i] * w1r.w;
            }
        }
        __syncthreads();
    }
    {
        float4 bv0 = *reinterpret_cast<const float4*>(b1 + lane * 4);
        float4 bv1 = *reinterpret_cast<const float4*>(b1 + 128 + lane * 4);
        #pragma unroll
        for (int i = 0; i < 4; ++i) {
            int r = wrp * 4 + i;
            float4 h0, h1;
            h0.x = fmaxf(acc1[i][0] + bv0.x, 0.f); h0.y = fmaxf(acc1[i][1] + bv0.y, 0.f);
            h0.z = fmaxf(acc1[i][2] + bv0.z, 0.f); h0.w = fmaxf(acc1[i][3] + bv0.w, 0.f);
            h1.x = fmaxf(acc1[i][4] + bv1.x, 0.f); h1.y = fmaxf(acc1[i][5] + bv1.y, 0.f);
            h1.z = fmaxf(acc1[i][6] + bv1.z, 0.f); h1.w = fmaxf(acc1[i][7] + bv1.w, 0.f);
            *reinterpret_cast<float4*>(&sH[r][lane * 4]) = h0;
            *reinterpret_cast<float4*>(&sH[r][128 + lane * 4]) = h1;
        }
    }
    __syncthreads();

    // ---- stage 2: C = H @ W2 + b2  (32 x 128) ----
    float acc2[4][4];
    #pragma unroll
    for (int i = 0; i < 4; ++i)
        #pragma unroll
        for (int j = 0; j < 4; ++j) acc2[i][j] = 0.f;

    for (int kt = 0; kt < HID; kt += BK) {
        {
            int k = tid >> 5, c4 = tid & 31;
            *reinterpret_cast<float4*>(&sW[k][c4 * 4]) =
                *reinterpret_cast<const float4*>(w2 + (size_t)(kt + k) * DIM + c4 * 4);
        }
        __syncthreads();
        #pragma unroll
        for (int k = 0; k < BK; ++k) {
            float ra[4];
            #pragma unroll
            for (int i = 0; i < 4; ++i) ra[i] = sH[wrp * 4 + i][kt + k];  // warp-broadcast
            float4 wv = *reinterpret_cast<const float4*>(&sW[k][lane * 4]);
            #pragma unroll
            for (int i = 0; i < 4; ++i) {
                acc2[i][0] += ra[i] * wv.x; acc2[i][1] += ra[i] * wv.y;
                acc2[i][2] += ra[i] * wv.z; acc2[i][3] += ra[i] * wv.w;
            }
        }
        __syncthreads();
    }
    // write C into sH storage (all stage-2 reads of sH are behind the last sync)
    float* sC = &sH[0][0];                        // [32][128], stride 128
    {
        float4 bv = *reinterpret_cast<const float4*>(b2 + lane * 4);
        #pragma unroll
        for (int i = 0; i < 4; ++i) {
            int r = wrp * 4 + i;
            float4 c;
            c.x = acc2[i][0] + bv.x; c.y = acc2[i][1] + bv.y;
            c.z = acc2[i][2] + bv.z; c.w = acc2[i][3] + bv.w;
            *reinterpret_cast<float4*>(sC + r * DIM + lane * 4) = c;
        }
    }
    __syncthreads();

    // ---- stage 3: per-row LN + sqrt-graphnorm + relu + residual ----
    // warp w handles rows w, w+8, w+16, w+24 (row index warp-uniform)
    #pragma unroll
    for (int rr = 0; rr < 4; ++rr) {
        int r = wrp + rr * 8;
        int u = rowBase + r;
        if (u >= M) continue;                     // warp-uniform
        float4 v = *reinterpret_cast<const float4*>(sC + r * DIM + lane * 4);
        float mu = warp_sum(v.x + v.y + v.z + v.w) * (1.f / DIM);
        float4 dv = make_float4(v.x - mu, v.y - mu, v.z - mu, v.w - mu);
        float var = warp_sum(dv.x * dv.x + dv.y * dv.y + dv.z * dv.z + dv.w * dv.w) * (1.f / DIM);
        float rstd = rsqrtf(var + LN_EPS);
        int g = gid[u];
        float gn = rsqrtf(warp_seg_count(gid, M, u, g, lane));
        float4 gg = *reinterpret_cast<const float4*>(lng + lane * 4);
        float4 bb = *reinterpret_cast<const float4*>(lnb + lane * 4);
        float4 y;
        y.x = fmaxf((dv.x * rstd * gg.x + bb.x) * gn, 0.f);
        y.y = fmaxf((dv.y * rstd * gg.y + bb.y) * gn, 0.f);
        y.z = fmaxf((dv.z * rstd * gg.z + bb.z) * gn, 0.f);
        y.w = fmaxf((dv.w * rstd * gg.w + bb.w) * gn, 0.f);

        if (EDGE) {
            // recompute bond_embed row u (residual)
            int e = 2 * u;
            float x = bond_float[e];
            float ev = 0.f;
            if (lane < NCB) {
                float dlt = x - 0.1f * (float)lane;
                ev = __expf(-GAMMA * dlt * dlt);
            }
            int c0 = bond_cat[(size_t)e * 3 + 0];
            int c1 = bond_cat[(size_t)e * 3 + 1];
            int c2 = bond_cat[(size_t)e * 3 + 2];
            float4 res = reinterpret_cast<const float4*>(rbfb)[lane];
            float4 t;
            t = reinterpret_cast<const float4*>(bemb + (size_t)(0 * 16 + c0) * DIM)[lane];
            res.x += t.x; res.y += t.y; res.z += t.z; res.w += t.w;
            t = reinterpret_cast<const float4*>(bemb + (size_t)(1 * 16 + c1) * DIM)[lane];
            res.x += t.x; res.y += t.y; res.z += t.z; res.w += t.w;
            t = reinterpret_cast<const float4*>(bemb + (size_t)(2 * 16 + c2) * DIM)[lane];
            res.x += t.x; res.y += t.y; res.z += t.z; res.w += t.w;
            #pragma unroll
            for (int c = 0; c < NCB; ++c) {
                float ec = __shfl_sync(0xFFFFFFFFu, ev, c);
                float4 wv = reinterpret_cast<const float4*>(rbfW + (size_t)c * DIM)[lane];
                res.x += ec * wv.x; res.y += ec * wv.y;
                res.z += ec * wv.z; res.w += ec * wv.w;
            }
            y.x += res.x; y.y += res.y; y.z += res.z; y.w += res.w;
            *reinterpret_cast<float4*>(out + (size_t)(2 * u) * DIM + lane * 4) = y;
            *reinterpret_cast<float4*>(out + (size_t)(2 * u + 1) * DIM + lane * 4) = y;
        } else {
            float4 res = reinterpret_cast<const float4*>(base + (size_t)u * DIM)[lane];
            y.x += res.x; y.y += res.y; y.z += res.z; y.w += res.w;
            *reinterpret_cast<float4*>(out + (size_t)u * DIM + lane * 4) = y;
        }
    }
}

// ---------------- launch ----------------
extern "C" void kernel_launch(void* const* d_in, const int* in_sizes, int n_in,
                              void* d_out, int out_size) {
    const float* node_feats  = (const float*)d_in[0];
    const float* edge_feats  = (const float*)d_in[1];
    const float* bond_float  = (const float*)d_in[2];
    const float* angle_float = (const float*)d_in[3];
    const float* bond_emb    = (const float*)d_in[4];
    const float* w1a = (const float*)d_in[5];
    const float* b1a = (const float*)d_in[6];
    const float* w2a = (const float*)d_in[7];
    const float* b2a = (const float*)d_in[8];
    const float* lng_a = (const float*)d_in[9];
    const float* lnb_a = (const float*)d_in[10];
    const float* w1b = (const float*)d_in[11];
    const float* b1b = (const float*)d_in[12];
    const float* w2b = (const float*)d_in[13];
    const float* b2b = (const float*)d_in[14];
    const float* lng_b = (const float*)d_in[15];
    const float* lnb_b = (const float*)d_in[16];
    const float* rbfb_W = (const float*)d_in[17];
    const float* rbfb_b = (const float*)d_in[18];
    const float* rbfa_W = (const float*)d_in[19];
    const float* rbfa_b = (const float*)d_in[20];
    const int* ab_src = (const int*)d_in[21];
    const int* ab_dst = (const int*)d_in[22];
    const int* ab_gid = (const int*)d_in[23];
    const int* ba_src = (const int*)d_in[24];
    const int* ba_dst = (const int*)d_in[25];
    const int* ba_gid = (const int*)d_in[26];
    const int* bond_cat = (const int*)d_in[27];

    float* outN = (float*)d_out;                        // NA*DIM floats
    float* outE = outN + (size_t)NA * DIM;              // NBD*DIM floats

    const int N4 = NA * DIM / 4;

    // ---- Phase E (edge block): node region = agg_b, edge rows [0,NB) = bond_embed ----
    k_zero<<<2048, 256>>>(reinterpret_cast<float4*>(outN), N4);
    k_bond_embed<<<(NB * 32 + 255) / 256, 256>>>(bond_float, bond_cat, bond_emb,
                                                 rbfb_W, rbfb_b, outE);
    k_scatter_b<<<(NANG * 32 + 255) / 256, 256>>>(angle_float, ba_src, ba_dst,
                                                  rbfa_W, rbfa_b, outE, outN);
    k_fused<1><<<(NB + 31) / 32, 256>>>(outN, w1b, b1b, w2b, b2b, lng_b, lnb_b,
                                        ba_gid, nullptr,
                                        bond_float, bond_cat, bond_emb, rbfb_W, rbfb_b,
                                        outE, NB);

    // ---- Phase N (node block): node region = agg_a, then node output in place ----
    k_zero<<<2048, 256>>>(reinterpret_cast<float4*>(outN), N4);
    k_scatter_a<<<(NBD * 32 + 255) / 256, 256>>>(node_feats, edge_feats, ab_src, ab_dst, outN);
    k_fused<0><<<(NA + 31) / 32, 256>>>(outN, w1a, b1a, w2a, b2a, lng_a, lnb_a,
                                        ab_gid, node_feats,
                                        nullptr, nullptr, nullptr, nullptr, nullptr,
                                        outN, NA);
}

// round 4
// speedup vs baseline: 1.6004x; 1.6004x over previous
#include <cuda_runtime.h>
#include <cstdint>
#include <math.h>

// ---------------- problem constants ----------------
#define NA    100000      // atoms
#define NBD   200000      // directed bonds
#define NB    100000      // undirected bonds
#define NANG  400000      // angles
#define NG    2048        // graphs
#define DIM   128         // embed dim
#define HID   256         // hidden dim (2*DIM)
#define NCB   20          // bond RBF centers
#define NCA   32          // angle RBF centers
#define GAMMA 10.0f
#define LN_EPS 1e-5f

// NO __device__ globals: all scratch lives inside d_out.
// d_out layout: [node region: NA*DIM floats][edge region: NBD*DIM floats]

// ---------------- helpers ----------------
__device__ __forceinline__ void red_add_v4(float* addr, float4 v) {
    asm volatile("red.global.add.v4.f32 [%0], {%1, %2, %3, %4};"
                 :: "l"(addr), "f"(v.x), "f"(v.y), "f"(v.z), "f"(v.w)
                 : "memory");
}

__device__ __forceinline__ float warp_sum(float v) {
    #pragma unroll
    for (int o = 16; o > 0; o >>= 1) v += __shfl_xor_sync(0xFFFFFFFFu, v, o);
    return v;
}

__device__ __forceinline__ unsigned f2tf32(float x) {
    unsigned r;
    asm("cvt.rna.tf32.f32 %0, %1;" : "=r"(r) : "f"(x));
    return r;
}

// D += A(16x8,row) * B(8x8,col)   tf32, fp32 accum
__device__ __forceinline__ void mma8(float& d0, float& d1, float& d2, float& d3,
                                     unsigned a0, unsigned a1, unsigned a2, unsigned a3,
                                     unsigned b0, unsigned b1) {
    asm volatile("mma.sync.aligned.m16n8k8.row.col.f32.tf32.tf32.f32 "
                 "{%0,%1,%2,%3}, {%4,%5,%6,%7}, {%8,%9}, {%0,%1,%2,%3};"
                 : "+f"(d0), "+f"(d1), "+f"(d2), "+f"(d3)
                 : "r"(a0), "r"(a1), "r"(a2), "r"(a3), "r"(b0), "r"(b1));
}

// segment length of the (sorted) gid array around index u (gid[u] == g).
__device__ __forceinline__ float warp_seg_count(const int* __restrict__ gid,
                                                int M, int u, int g, int lane) {
    int r = u + 1;
    for (;;) {
        int i = r + lane;
        int v = (i < M) ? gid[i] : (g ^ 1);
        unsigned m = __ballot_sync(0xFFFFFFFFu, v != g);
        if (m) { r += __ffs(m) - 1; break; }
        r += 32;
    }
    int l = u - 1;
    for (;;) {
        int i = l - lane;
        int v = (i >= 0) ? gid[i] : (g ^ 1);
        unsigned m = __ballot_sync(0xFFFFFFFFu, v != g);
        if (m) { l -= __ffs(m) - 1; break; }
        l -= 32;
    }
    return (float)(r - l - 1);
}

// ---------------- zero a float4 range ----------------
__global__ void k_zero(float4* __restrict__ p, int n4) {
    int stride = gridDim.x * blockDim.x;
    float4 z = make_float4(0.f, 0.f, 0.f, 0.f);
    for (int i = blockIdx.x * blockDim.x + threadIdx.x; i < n4; i += stride) p[i] = z;
}

// ---------------- block A scatter: agg[dst] += nf[src] + ef[e] ----------------
__global__ void k_scatter_a(const float* __restrict__ nf, const float* __restrict__ ef,
                            const int* __restrict__ src, const int* __restrict__ dst,
                            float* __restrict__ agg) {
    int w = (blockIdx.x * blockDim.x + threadIdx.x) >> 5;
    int lane = threadIdx.x & 31;
    if (w >= NBD) return;
    int s = __ldg(&src[w]);
    int d = __ldg(&dst[w]);
    float4 a = reinterpret_cast<const float4*>(nf + (size_t)s * DIM)[lane];
    float4 b = reinterpret_cast<const float4*>(ef + (size_t)w * DIM)[lane];
    float4 v = make_float4(a.x + b.x, a.y + b.y, a.z + b.z, a.w + b.w);
    red_add_v4(agg + (size_t)d * DIM + lane * 4, v);
}

// ---------------- bond embedding (even directed bonds) -> bond_embed[u] ------
__global__ void k_bond_embed(const float* __restrict__ bond_float,
                             const int* __restrict__ bond_cat,
                             const float* __restrict__ bemb,
                             const float* __restrict__ rbfW,
                             const float* __restrict__ rbfb,
                             float* __restrict__ bond_embed) {
    int u = (blockIdx.x * blockDim.x + threadIdx.x) >> 5;
    int lane = threadIdx.x & 31;
    if (u >= NB) return;
    int e = 2 * u;
    float x = __ldg(&bond_float[e]);
    float ev = 0.f;
    if (lane < NCB) {
        float dlt = x - 0.1f * (float)lane;
        ev = __expf(-GAMMA * dlt * dlt);
    }
    int c0 = __ldg(&bond_cat[(size_t)e * 3 + 0]);
    int c1 = __ldg(&bond_cat[(size_t)e * 3 + 1]);
    int c2 = __ldg(&bond_cat[(size_t)e * 3 + 2]);

    float4 acc = reinterpret_cast<const float4*>(rbfb)[lane];
    float4 t;
    t = reinterpret_cast<const float4*>(bemb + (size_t)(0 * 16 + c0) * DIM)[lane];
    acc.x += t.x; acc.y += t.y; acc.z += t.z; acc.w += t.w;
    t = reinterpret_cast<const float4*>(bemb + (size_t)(1 * 16 + c1) * DIM)[lane];
    acc.x += t.x; acc.y += t.y; acc.z += t.z; acc.w += t.w;
    t = reinterpret_cast<const float4*>(bemb + (size_t)(2 * 16 + c2) * DIM)[lane];
    acc.x += t.x; acc.y += t.y; acc.z += t.z; acc.w += t.w;

    #pragma unroll
    for (int c = 0; c < NCB; ++c) {
        float ec = __shfl_sync(0xFFFFFFFFu, ev, c);
        float4 wv = reinterpret_cast<const float4*>(rbfW + (size_t)c * DIM)[lane];
        acc.x += ec * wv.x; acc.y += ec * wv.y; acc.z += ec * wv.z; acc.w += ec * wv.w;
    }
    reinterpret_cast<float4*>(bond_embed + (size_t)u * DIM)[lane] = acc;
}

// ---------------- block B scatter: agg[dst] += bond_embed[src] + rbf(angle) ---
__global__ void k_scatter_b(const float* __restrict__ angle_float,
                            const int* __restrict__ src, const int* __restrict__ dst,
                            const float* __restrict__ rbfW,
                            const float* __restrict__ rbfb,
                            const float* __restrict__ bond_embed,
                            float* __restrict__ agg) {
    int a = (blockIdx.x * blockDim.x + threadIdx.x) >> 5;
    int lane = threadIdx.x & 31;
    if (a >= NANG) return;
    float x = __ldg(&angle_float[a]);
    float dlt = x - 0.1f * (float)lane;
    float ev = __expf(-GAMMA * dlt * dlt);
    int s = __ldg(&src[a]);
    int d = __ldg(&dst[a]);

    float4 acc = reinterpret_cast<const float4*>(rbfb)[lane];
    float4 be = reinterpret_cast<const float4*>(bond_embed + (size_t)s * DIM)[lane];
    acc.x += be.x; acc.y += be.y; acc.z += be.z; acc.w += be.w;

    #pragma unroll
    for (int c = 0; c < NCA; ++c) {
        float ec = __shfl_sync(0xFFFFFFFFu, ev, c);
        float4 wv = reinterpret_cast<const float4*>(rbfW + (size_t)c * DIM)[lane];
        acc.x += ec * wv.x; acc.y += ec * wv.y; acc.z += ec * wv.z; acc.w += ec * wv.w;
    }
    red_add_v4(agg + (size_t)d * DIM + lane * 4, acc);
}

// ---------------- fused tf32-MMA MLP + LN + graphnorm + relu + residual -------
// BM=32 rows/block, 256 threads (8 warps). Requires M % 32 == 0 (holds: 100000).
// smem union (uint32 indices):
//   OFF_A  = 0     : sA  [32][132]  tf32 A tile           (4224)
//   OFF_W1 = 4224  : sW1 [16][264]  tf32 W1 k-chunk       (4224)
//   OFF_H  = 0     : sH  [32][260]  tf32 hidden (reuses A+W1 region, 8320<=8448)
//   OFF_W2 = 8448  : sW2 [16][136]  tf32 W2 k-chunk       (2176)
//   OFF_C  = 0     : sC  [32][132]  fp32 output (reuses sH region)
// total 10624 u32 = 42.5 KB static.
#define OFF_A  0
#define OFF_W1 4224
#define OFF_H  0
#define OFF_W2 8448
#define OFF_C  0
#define SMEM_U32 10624

template<int EDGE>
__global__ void __launch_bounds__(256)
k_fused(const float* __restrict__ A,
        const float* __restrict__ w1, const float* __restrict__ b1,
        const float* __restrict__ w2, const float* __restrict__ b2,
        const float* __restrict__ lng, const float* __restrict__ lnb,
        const int* __restrict__ gid,
        const float* __restrict__ base,
        const float* __restrict__ bond_float, const int* __restrict__ bond_cat,
        const float* __restrict__ bemb,
        const float* __restrict__ rbfW, const float* __restrict__ rbfb,
        float* __restrict__ out, int M) {
    __shared__ unsigned sm[SMEM_U32];
    float* smf = reinterpret_cast<float*>(sm);

    const int tid  = threadIdx.x;
    const int lane = tid & 31;
    const int wrp  = tid >> 5;         // 0..7
    const int rowBase = blockIdx.x * 32;
    const int tig  = lane & 3;         // threadID_in_group
    const int grp  = lane >> 2;        // groupID

    // ---- load A tile [32][128] -> sA (tf32), coalesced ----
    #pragma unroll
    for (int i = 0; i < 4; ++i) {
        int idx = tid + i * 256;              // 0..1023 float4s
        int row = idx >> 5;                   // 0..31
        int c4  = (idx & 31) * 4;
        float4 v = *reinterpret_cast<const float4*>(A + (size_t)(rowBase + row) * DIM + c4);
        uint4 u = make_uint4(f2tf32(v.x), f2tf32(v.y), f2tf32(v.z), f2tf32(v.w));
        *reinterpret_cast<uint4*>(&sm[OFF_A + row * 132 + c4]) = u;
    }

    // ---- stage 1: H[32][256] = relu(A @ W1 + b1), warp n-tile = 32 cols ----
    float d1[2][4][4];
    #pragma unroll
    for (int mt = 0; mt < 2; ++mt)
        #pragma unroll
        for (int nt = 0; nt < 4; ++nt)
            #pragma unroll
            for (int c = 0; c < 4; ++c) d1[mt][nt][c] = 0.f;

    for (int kc = 0; kc < 8; ++kc) {          // K=128 in chunks of 16
        // load W1 rows [kc*16, kc*16+16) x 256 -> sW1 (tf32)
        #pragma unroll
        for (int i = 0; i < 4; ++i) {
            int idx = tid + i * 256;          // 0..1023 float4s
            int row = idx >> 6;               // 0..15
            int c4  = (idx & 63) * 4;
            float4 v = *reinterpret_cast<const float4*>(w1 + (size_t)(kc * 16 + row) * HID + c4);
            uint4 u = make_uint4(f2tf32(v.x), f2tf32(v.y), f2tf32(v.z), f2tf32(v.w));
            *reinterpret_cast<uint4*>(&sm[OFF_W1 + row * 264 + c4]) = u;
        }
        __syncthreads();

        #pragma unroll
        for (int ks = 0; ks < 2; ++ks) {
            int kg = kc * 16 + ks * 8 + tig;  // global k col in sA
            int kl = ks * 8 + tig;            // local k row in sW1
            unsigned a[2][4];
            #pragma unroll
            for (int mt = 0; mt < 2; ++mt) {
                int r = grp + mt * 16;
                a[mt][0] = sm[OFF_A + r * 132 + kg];
                a[mt][1] = sm[OFF_A + (r + 8) * 132 + kg];
                a[mt][2] = sm[OFF_A + r * 132 + kg + 4];
                a[mt][3] = sm[OFF_A + (r + 8) * 132 + kg + 4];
            }
            #pragma unroll
            for (int nt = 0; nt < 4; ++nt) {
                int n = wrp * 32 + nt * 8 + grp;
                unsigned b0 = sm[OFF_W1 + kl * 264 + n];
                unsigned b1f = sm[OFF_W1 + (kl + 4) * 264 + n];
                mma8(d1[0][nt][0], d1[0][nt][1], d1[0][nt][2], d1[0][nt][3],
                     a[0][0], a[0][1], a[0][2], a[0][3], b0, b1f);
                mma8(d1[1][nt][0], d1[1][nt][1], d1[1][nt][2], d1[1][nt][3],
                     a[1][0], a[1][1], a[1][2], a[1][3], b0, b1f);
            }
        }
        __syncthreads();
    }

    // ---- H epilogue: bias + relu, store tf32 to sH (overlaps sA/sW1) ----
    #pragma unroll
    for (int nt = 0; nt < 4; ++nt) {
        int col = wrp * 32 + nt * 8 + 2 * tig;
        float bb0 = b1[col], bb1 = b1[col + 1];
        #pragma unroll
        for (int mt = 0; mt < 2; ++mt) {
            int r0 = grp + mt * 16;
            float h00 = fmaxf(d1[mt][nt][0] + bb0, 0.f);
            float h01 = fmaxf(d1[mt][nt][1] + bb1, 0.f);
            float h10 = fmaxf(d1[mt][nt][2] + bb0, 0.f);
            float h11 = fmaxf(d1[mt][nt][3] + bb1, 0.f);
            *reinterpret_cast<uint2*>(&sm[OFF_H + r0 * 260 + col]) =
                make_uint2(f2tf32(h00), f2tf32(h01));
            *reinterpret_cast<uint2*>(&sm[OFF_H + (r0 + 8) * 260 + col]) =
                make_uint2(f2tf32(h10), f2tf32(h11));
        }
    }
    __syncthreads();

    // ---- stage 2: C[32][128] = H @ W2 + b2, warp n-tile = 16 cols ----
    float d2[2][2][4];
    #pragma unroll
    for (int mt = 0; mt < 2; ++mt)
        #pragma unroll
        for (int nt = 0; nt < 2; ++nt)
            #pragma unroll
            for (int c = 0; c < 4; ++c) d2[mt][nt][c] = 0.f;

    for (int kc = 0; kc < 16; ++kc) {         // K=256 in chunks of 16
        #pragma unroll
        for (int i = 0; i < 2; ++i) {
            int idx = tid + i * 256;          // 0..511 float4s
            int row = idx >> 5;               // 0..15
            int c4  = (idx & 31) * 4;
            float4 v = *reinterpret_cast<const float4*>(w2 + (size_t)(kc * 16 + row) * DIM + c4);
            uint4 u = make_uint4(f2tf32(v.x), f2tf32(v.y), f2tf32(v.z), f2tf32(v.w));
            *reinterpret_cast<uint4*>(&sm[OFF_W2 + row * 136 + c4]) = u;
        }
        __syncthreads();

        #pragma unroll
        for (int ks = 0; ks < 2; ++ks) {
            int kg = kc * 16 + ks * 8 + tig;  // col in sH
            int kl = ks * 8 + tig;            // row in sW2
            unsigned a[2][4];
            #pragma unroll
            for (int mt = 0; mt < 2; ++mt) {
                int r = grp + mt * 16;
                a[mt][0] = sm[OFF_H + r * 260 + kg];
                a[mt][1] = sm[OFF_H + (r + 8) * 260 + kg];
                a[mt][2] = sm[OFF_H + r * 260 + kg + 4];
                a[mt][3] = sm[OFF_H + (r + 8) * 260 + kg + 4];
            }
            #pragma unroll
            for (int nt = 0; nt < 2; ++nt) {
                int n = wrp * 16 + nt * 8 + grp;
                unsigned b0 = sm[OFF_W2 + kl * 136 + n];
                unsigned b1f = sm[OFF_W2 + (kl + 4) * 136 + n];
                mma8(d2[0][nt][0], d2[0][nt][1], d2[0][nt][2], d2[0][nt][3],
                     a[0][0], a[0][1], a[0][2], a[0][3], b0, b1f);
                mma8(d2[1][nt][0], d2[1][nt][1], d2[1][nt][2], d2[1][nt][3],
                     a[1][0], a[1][1], a[1][2], a[1][3], b0, b1f);
            }
        }
        __syncthreads();
    }

    // ---- C epilogue: bias, store fp32 to sC (overlaps sH region) ----
    #pragma unroll
    for (int nt = 0; nt < 2; ++nt) {
        int col = wrp * 16 + nt * 8 + 2 * tig;
        float bb0 = b2[col], bb1 = b2[col + 1];
        #pragma unroll
        for (int mt = 0; mt < 2; ++mt) {
            int r0 = grp + mt * 16;
            *reinterpret_cast<float2*>(&smf[OFF_C + r0 * 132 + col]) =
                make_float2(d2[mt][nt][0] + bb0, d2[mt][nt][1] + bb1);
            *reinterpret_cast<float2*>(&smf[OFF_C + (r0 + 8) * 132 + col]) =
                make_float2(d2[mt][nt][2] + bb0, d2[mt][nt][3] + bb1);
        }
    }
    __syncthreads();

    // ---- stage 3: per-row LN + sqrt-graphnorm + relu + residual ----
    #pragma unroll
    for (int rr = 0; rr < 4; ++rr) {
        int r = wrp + rr * 8;
        int u = rowBase + r;
        float4 v = *reinterpret_cast<const float4*>(&smf[OFF_C + r * 132 + lane * 4]);
        float mu = warp_sum(v.x + v.y + v.z + v.w) * (1.f / DIM);
        float4 dv = make_float4(v.x - mu, v.y - mu, v.z - mu, v.w - mu);
        float var = warp_sum(dv.x * dv.x + dv.y * dv.y + dv.z * dv.z + dv.w * dv.w) * (1.f / DIM);
        float rstd = rsqrtf(var + LN_EPS);
        int g = gid[u];
        float gn = rsqrtf(warp_seg_count(gid, M, u, g, lane));
        float4 gg = *reinterpret_cast<const float4*>(lng + lane * 4);
        float4 bb = *reinterpret_cast<const float4*>(lnb + lane * 4);
        float4 y;
        y.x = fmaxf((dv.x * rstd * gg.x + bb.x) * gn, 0.f);
        y.y = fmaxf((dv.y * rstd * gg.y + bb.y) * gn, 0.f);
        y.z = fmaxf((dv.z * rstd * gg.z + bb.z) * gn, 0.f);
        y.w = fmaxf((dv.w * rstd * gg.w + bb.w) * gn, 0.f);

        if (EDGE) {
            // recompute bond_embed row u (residual)
            int e = 2 * u;
            float x = bond_float[e];
            float ev = 0.f;
            if (lane < NCB) {
                float dlt = x - 0.1f * (float)lane;
                ev = __expf(-GAMMA * dlt * dlt);
            }
            int c0 = bond_cat[(size_t)e * 3 + 0];
            int c1 = bond_cat[(size_t)e * 3 + 1];
            int c2 = bond_cat[(size_t)e * 3 + 2];
            float4 res = reinterpret_cast<const float4*>(rbfb)[lane];
            float4 t;
            t = reinterpret_cast<const float4*>(bemb + (size_t)(0 * 16 + c0) * DIM)[lane];
            res.x += t.x; res.y += t.y; res.z += t.z; res.w += t.w;
            t = reinterpret_cast<const float4*>(bemb + (size_t)(1 * 16 + c1) * DIM)[lane];
            res.x += t.x; res.y += t.y; res.z += t.z; res.w += t.w;
            t = reinterpret_cast<const float4*>(bemb + (size_t)(2 * 16 + c2) * DIM)[lane];
            res.x += t.x; res.y += t.y; res.z += t.z; res.w += t.w;
            #pragma unroll
            for (int c = 0; c < NCB; ++c) {
                float ec = __shfl_sync(0xFFFFFFFFu, ev, c);
                float4 wv = reinterpret_cast<const float4*>(rbfW + (size_t)c * DIM)[lane];
                res.x += ec * wv.x; res.y += ec * wv.y;
                res.z += ec * wv.z; res.w += ec * wv.w;
            }
            y.x += res.x; y.y += res.y; y.z += res.z; y.w += res.w;
            *reinterpret_cast<float4*>(out + (size_t)(2 * u) * DIM + lane * 4) = y;
            *reinterpret_cast<float4*>(out + (size_t)(2 * u + 1) * DIM + lane * 4) = y;
        } else {
            float4 res = reinterpret_cast<const float4*>(base + (size_t)u * DIM)[lane];
            y.x += res.x; y.y += res.y; y.z += res.z; y.w += res.w;
            *reinterpret_cast<float4*>(out + (size_t)u * DIM + lane * 4) = y;
        }
    }
}

// ---------------- launch ----------------
extern "C" void kernel_launch(void* const* d_in, const int* in_sizes, int n_in,
                              void* d_out, int out_size) {
    const float* node_feats  = (const float*)d_in[0];
    const float* edge_feats  = (const float*)d_in[1];
    const float* bond_float  = (const float*)d_in[2];
    const float* angle_float = (const float*)d_in[3];
    const float* bond_emb    = (const float*)d_in[4];
    const float* w1a = (const float*)d_in[5];
    const float* b1a = (const float*)d_in[6];
    const float* w2a = (const float*)d_in[7];
    const float* b2a = (const float*)d_in[8];
    const float* lng_a = (const float*)d_in[9];
    const float* lnb_a = (const float*)d_in[10];
    const float* w1b = (const float*)d_in[11];
    const float* b1b = (const float*)d_in[12];
    const float* w2b = (const float*)d_in[13];
    const float* b2b = (const float*)d_in[14];
    const float* lng_b = (const float*)d_in[15];
    const float* lnb_b = (const float*)d_in[16];
    const float* rbfb_W = (const float*)d_in[17];
    const float* rbfb_b = (const float*)d_in[18];
    const float* rbfa_W = (const float*)d_in[19];
    const float* rbfa_b = (const float*)d_in[20];
    const int* ab_src = (const int*)d_in[21];
    const int* ab_dst = (const int*)d_in[22];
    const int* ab_gid = (const int*)d_in[23];
    const int* ba_src = (const int*)d_in[24];
    const int* ba_dst = (const int*)d_in[25];
    const int* ba_gid = (const int*)d_in[26];
    const int* bond_cat = (const int*)d_in[27];

    float* outN = (float*)d_out;                        // NA*DIM floats
    float* outE = outN + (size_t)NA * DIM;              // NBD*DIM floats

    const int N4 = NA * DIM / 4;

    // ---- Phase E (edge block): node region = agg_b, edge rows [0,NB) = bond_embed ----
    k_zero<<<2048, 256>>>(reinterpret_cast<float4*>(outN), N4);
    k_bond_embed<<<(NB * 32 + 255) / 256, 256>>>(bond_float, bond_cat, bond_emb,
                                                 rbfb_W, rbfb_b, outE);
    k_scatter_b<<<(NANG * 32 + 255) / 256, 256>>>(angle_float, ba_src, ba_dst,
                                                  rbfa_W, rbfa_b, outE, outN);
    k_fused<1><<<NB / 32, 256>>>(outN, w1b, b1b, w2b, b2b, lng_b, lnb_b,
                                 ba_gid, nullptr,
                                 bond_float, bond_cat, bond_emb, rbfb_W, rbfb_b,
                                 outE, NB);

    // ---- Phase N (node block): node region = agg_a, then node output in place ----
    k_zero<<<2048, 256>>>(reinterpret_cast<float4*>(outN), N4);
    k_scatter_a<<<(NBD * 32 + 255) / 256, 256>>>(node_feats, edge_feats, ab_src, ab_dst, outN);
    k_fused<0><<<NA / 32, 256>>>(outN, w1a, b1a, w2a, b2a, lng_a, lnb_a,
                                 ab_gid, node_feats,
                                 nullptr, nullptr, nullptr, nullptr, nullptr,
                                 outN, NA);
}